// round 15
// baseline (speedup 1.0000x reference)
#include <cuda_runtime.h>
#include <cuda_fp16.h>
#include <cstdint>
#include <stdint.h>
#include <math.h>

#define NN 2048
#define KK 14
#define CC 512
#define OO 512
#define EE 78
#define BN_EPS 1e-5f
#define MTOT (NN * KK)     // 28672

// ---------------- device scratch ----------------
__device__ float g_S1[CC];
__device__ float g_Q[CC];
__device__ __half g_Ah[(size_t)MTOT * CC];     // fp16 X    (28 MB)
__device__ __half g_Ag[(size_t)MTOT * CC];     // fp16 agg  (28 MB)
__device__ __half g_Bh[2ull * OO * CC];        // fp16 Wo(0), Wm(1)

__device__ __forceinline__ uint32_t h2u(__half2 h) { return *reinterpret_cast<uint32_t*>(&h); }

#define LDSM_X4(r, addr)                                                      \
    asm volatile("ldmatrix.sync.aligned.m8n8.x4.shared.b16 {%0,%1,%2,%3}, [%4];" \
                 : "=r"((r)[0]), "=r"((r)[1]), "=r"((r)[2]), "=r"((r)[3])     \
                 : "r"(addr))
#define MMA_F16(Cr, A0, A1, A2, A3, B0, B1)                                   \
    asm volatile("mma.sync.aligned.m16n8k16.row.col.f32.f16.f16.f32 "          \
                 "{%0,%1,%2,%3}, {%4,%5,%6,%7}, {%8,%9}, {%0,%1,%2,%3};\n"     \
                 : "+f"(Cr[0]), "+f"(Cr[1]), "+f"(Cr[2]), "+f"(Cr[3])          \
                 : "r"(A0), "r"(A1), "r"(A2), "r"(A3), "r"(B0), "r"(B1))
// fp16-accumulate variant: D,C are 2x .f16x2 regs
#define MMA_H16(D0, D1, A0, A1, A2, A3, B0, B1, C0, C1)                        \
    asm volatile("mma.sync.aligned.m16n8k16.row.col.f16.f16.f16.f16 "          \
                 "{%0,%1}, {%2,%3,%4,%5}, {%6,%7}, {%8,%9};\n"                 \
                 : "=r"(D0), "=r"(D1)                                          \
                 : "r"(A0), "r"(A1), "r"(A2), "r"(A3), "r"(B0), "r"(B1),       \
                   "r"(C0), "r"(C1))

// ---------------- pack weights to fp16 (+ zero stats in block 0) ----------------
__global__ __launch_bounds__(256) void k_packw(const float* __restrict__ Wm,
                                               const float* __restrict__ Wo) {
    if (blockIdx.x == 0) {
        int t = threadIdx.x;
        g_S1[t] = 0.f; g_S1[t + 256] = 0.f;
        g_Q[t]  = 0.f; g_Q[t + 256]  = 0.f;
    }
    int i = blockIdx.x * 1024 + threadIdx.x;
#pragma unroll
    for (int r = 0; r < 4; r++, i += 256) {
        g_Bh[i]           = __float2half(Wo[i]);
        g_Bh[OO * CC + i] = __float2half(Wm[i]);
    }
}

// ---------------- per-channel BN statistics + fp16 pack of X (R13 proven) ----------------
__global__ __launch_bounds__(512) void k_stats(const float* __restrict__ x) {
    int c = threadIdx.x;
    int n0 = blockIdx.x * 8;
    float s1a = 0.f, qa = 0.f;
    for (int r = 0; r < 8; r++) {
        int n = n0 + r;
        const float* p = x + (size_t)n * (KK * CC) + c;
        __half* ah = g_Ah + ((size_t)n * KK) * CC + c;
        float g = p[13 * CC];
        ah[13 * CC] = __float2half(g);
        float s1 = 0.f, s2 = 0.f, ws = 0.f;
#pragma unroll
        for (int k = 0; k < 13; k++) {
            float v = p[k * CC];
            ah[k * CC] = __float2half(v);
            float d = fabsf(v - g);
            s1 += d;
            s2 += d * d;
            ws += (float)(12 - 2 * k) * d;
        }
        s1a += ws;
        qa  += 13.f * s2 - s1 * s1;
    }
    atomicAdd(&g_S1[c], s1a);
    atomicAdd(&g_Q[c],  qa);
}

// ---------------- adjacency + tensor-core aggregation (R13 proven, 512 thr) ----------------
__global__ __launch_bounds__(512, 3) void k_adjW(const float* __restrict__ adjin,
                                                 const int* __restrict__ ei,
                                                 const int* __restrict__ ej,
                                                 const float* __restrict__ gamma,
                                                 const float* __restrict__ beta,
                                                 const float* __restrict__ wdir) {
    int n = blockIdx.x;
    int c = threadIdx.x;
    int lane = c & 31, warp = c >> 5;

    __shared__ char buf[13 * 512 * 4];
    __shared__ float red[16];
    __shared__ float s_cst;
    __shared__ float sp[13];
    __shared__ float W[14][14];
    __shared__ float rn[14];
    __shared__ __half Whi[16][24];
    __shared__ __half Wlo[16][24];

    float (*sd)[CC] = (float (*)[CC])buf;

    const float inv = 1.f / (float)((size_t)NN * EE);
    float mean = 15.f * g_S1[c] * inv;
    float ms   = 225.f * g_Q[c] * inv;
    float var  = ms - mean * mean;
    float w    = wdir[c];
    float u    = gamma[c] * rsqrtf(var + BN_EPS) * w;
    float part = beta[c] * w - mean * u;
#pragma unroll
    for (int off = 16; off > 0; off >>= 1)
        part += __shfl_xor_sync(0xffffffffu, part, off);
    if (lane == 0) red[warp] = part;

    const __half* ah = g_Ah + ((size_t)n * KK) * CC + c;
    __half hv[14];
#pragma unroll
    for (int k = 0; k < 14; k++) hv[k] = ah[k * CC];
    {
        float g = __half2float(hv[13]);
#pragma unroll
        for (int k = 0; k < 13; k++)
            sd[k][c] = fabsf(__half2float(hv[k]) - g) * u;
    }
    if (c < 196) W[c / 14][c % 14] = adjin[c];
    __syncthreads();

    if (c == 0) {
        float s = 0.f;
#pragma unroll
        for (int i = 0; i < 16; i++) s += red[i];
        s_cst = s;
    }
    if (warp < 13) {
        float s = 0.f;
#pragma unroll
        for (int i = 0; i < 16; i++) s += sd[warp][lane + 32 * i];
        s += __shfl_xor_sync(0xffffffffu, s, 16);
        s += __shfl_xor_sync(0xffffffffu, s, 8);
        s += __shfl_xor_sync(0xffffffffu, s, 4);
        s += __shfl_xor_sync(0xffffffffu, s, 2);
        s += __shfl_xor_sync(0xffffffffu, s, 1);
        if (lane == 0) sp[warp] = s;
    }
    __syncthreads();

    if (c < EE) {
        int i = ei[c], j = ej[c];
        float z = 15.f * (sp[i] - sp[j]) + s_cst;
        float a = 1.f / (1.f + expf(-4.f * z));
        W[i][j] = 2.f * a * adjin[i * 14 + j];
        W[j][i] = 2.f * (1.f - a) * adjin[j * 14 + i];
    }
    {
        char* row = buf + (size_t)c * 48;
        uint4 u0, u1;
        u0.x = h2u(__halves2half2(hv[0],  hv[1]));
        u0.y = h2u(__halves2half2(hv[2],  hv[3]));
        u0.z = h2u(__halves2half2(hv[4],  hv[5]));
        u0.w = h2u(__halves2half2(hv[6],  hv[7]));
        u1.x = h2u(__halves2half2(hv[8],  hv[9]));
        u1.y = h2u(__halves2half2(hv[10], hv[11]));
        u1.z = h2u(__halves2half2(hv[12], hv[13]));
        u1.w = 0u;
        *(uint4*)row        = u0;
        *(uint4*)(row + 16) = u1;
    }
    __syncthreads();

    if (c < 14) {
        float s = 0.f;
#pragma unroll
        for (int j = 0; j < 14; j++) s += fabsf(W[c][j]);
        rn[c] = 1.f / fmaxf(s, 1e-12f);
    }
    __syncthreads();

    if (c < 256) {
        int i = c >> 4, j = c & 15;
        float v = (i < 14 && j < 14) ? W[i][j] * rn[i] : 0.f;
        __half hi = __float2half(v);
        Whi[i][j] = hi;
        Wlo[i][j] = __float2half(v - __half2float(hi));
    }
    __syncthreads();

    {
        int lr = lane & 15, lh = lane >> 4;
        uint32_t xsb  = (uint32_t)__cvta_generic_to_shared(buf);
        uint32_t whib = (uint32_t)__cvta_generic_to_shared(&Whi[0][0]);
        uint32_t wlob = (uint32_t)__cvta_generic_to_shared(&Wlo[0][0]);
        uint32_t aw = (uint32_t)(lr * 48 + lh * 16);
        uint32_t bx0 = xsb + (uint32_t)((warp * 32 + lr) * 48 + lh * 16);
        uint32_t bx1 = bx0 + 16 * 48;

        uint32_t ahi[4], alo[4], bf0[4], bf1[4];
        LDSM_X4(ahi, whib + aw);
        LDSM_X4(alo, wlob + aw);
        LDSM_X4(bf0, bx0);
        LDSM_X4(bf1, bx1);

        float acc[4][4];
#pragma unroll
        for (int t = 0; t < 4; t++)
#pragma unroll
            for (int i = 0; i < 4; i++) acc[t][i] = 0.f;

        MMA_F16(acc[0], ahi[0], ahi[1], ahi[2], ahi[3], bf0[0], bf0[2]);
        MMA_F16(acc[0], alo[0], alo[1], alo[2], alo[3], bf0[0], bf0[2]);
        MMA_F16(acc[1], ahi[0], ahi[1], ahi[2], ahi[3], bf0[1], bf0[3]);
        MMA_F16(acc[1], alo[0], alo[1], alo[2], alo[3], bf0[1], bf0[3]);
        MMA_F16(acc[2], ahi[0], ahi[1], ahi[2], ahi[3], bf1[0], bf1[2]);
        MMA_F16(acc[2], alo[0], alo[1], alo[2], alo[3], bf1[0], bf1[2]);
        MMA_F16(acc[3], ahi[0], ahi[1], ahi[2], ahi[3], bf1[1], bf1[3]);
        MMA_F16(acc[3], alo[0], alo[1], alo[2], alo[3], bf1[1], bf1[3]);

        int gid = lane >> 2, tig = lane & 3;
        __half* ag = g_Ag + ((size_t)n * KK) * CC;
#pragma unroll
        for (int t = 0; t < 4; t++) {
            int col = warp * 32 + t * 8 + tig * 2;
            *(__half2*)&ag[(size_t)gid * CC + col] = __floats2half2_rn(acc[t][0], acc[t][1]);
            if (gid + 8 < 14)
                *(__half2*)&ag[(size_t)(gid + 8) * CC + col] = __floats2half2_rn(acc[t][2], acc[t][3]);
        }
    }
}

// ---------------- fused dual GEMM: fp16-accum chained MMA, promote per K=64 chunk ----------------
// Block 64x128, 8 warps = warp-per-matrix (2m x 2n x 2mat), warp 32x64 of ONE matrix.
#define S_AX 0
#define S_AG 8192
#define S_BO 16384
#define S_BM 32768
#define STG  49152
#define SMEM_G (2 * STG)   // 98304
#define LDE 132            // epilogue exchange stride (floats)

__device__ __forceinline__ void cpa16(uint32_t dst, const void* src) {
    asm volatile("cp.async.cg.shared.global [%0], [%1], 16;" :: "r"(dst), "l"(src));
}

__device__ __forceinline__ void g_load_chunk(uint32_t sb, int stg, int t,
                                             int m0, int o0, int tid) {
    uint32_t base = sb + (uint32_t)stg * STG;
    const __half* Ax = g_Ah + (size_t)m0 * CC + t * 64;
    const __half* Ag = g_Ag + (size_t)m0 * CC + t * 64;
    const __half* Bo = g_Bh + t * 64;
    const __half* Bm = g_Bh + (size_t)OO * CC + t * 64;
#pragma unroll
    for (int i = 0; i < 2; i++) {
        int idx = tid + i * 256;
        int r = idx >> 3, c = idx & 7;
        uint32_t off = (uint32_t)r * 128 + (uint32_t)c * 16;
        uint32_t sw = off ^ ((off >> 3) & 0x70);
        cpa16(base + S_AX + sw, Ax + (size_t)r * CC + c * 8);
        cpa16(base + S_AG + sw, Ag + (size_t)r * CC + c * 8);
    }
#pragma unroll
    for (int i = 0; i < 4; i++) {
        int idx = tid + i * 256;
        int r = idx >> 3, c = idx & 7;
        uint32_t off = (uint32_t)r * 128 + (uint32_t)c * 16;
        uint32_t sw = off ^ ((off >> 3) & 0x70);
        cpa16(base + S_BO + sw, Bo + (size_t)(o0 + r) * CC + c * 8);
        cpa16(base + S_BM + sw, Bm + (size_t)(o0 + r) * CC + c * 8);
    }
}

__global__ __launch_bounds__(256, 2) void k_gemm(float* __restrict__ out) {
    extern __shared__ char smem[];
    uint32_t sb = (uint32_t)__cvta_generic_to_shared(smem);
    int tid = threadIdx.x;
    int w = tid >> 5, l = tid & 31;
    int wi = w & 3;
    int wm = wi & 1;       // m half (32 rows)
    int wn = wi >> 1;      // n half (64 cols)
    int wmat = w >> 2;     // 0 = original (Ax@Wo), 1 = merged (Ag@Wm)
    int m0 = blockIdx.x * 64;
    int o0 = blockIdx.y * 128;
    int lr = l & 15, lh = l >> 4;

    float accf[2][8][4];
#pragma unroll
    for (int mt = 0; mt < 2; mt++)
#pragma unroll
        for (int nt = 0; nt < 8; nt++)
#pragma unroll
            for (int i = 0; i < 4; i++) accf[mt][nt][i] = 0.f;

    uint32_t sAoff = wmat ? S_AG : S_AX;
    uint32_t sBoff = wmat ? S_BM : S_BO;

    g_load_chunk(sb, 0, 0, m0, o0, tid);
    asm volatile("cp.async.commit_group;" ::: "memory");
    g_load_chunk(sb, 1, 1, m0, o0, tid);
    asm volatile("cp.async.commit_group;" ::: "memory");

    const int NCH = CC / 64;   // 8
    for (int t = 0; t < NCH; t++) {
        int b = t & 1;
        if (t < NCH - 1) asm volatile("cp.async.wait_group 1;" ::: "memory");
        else             asm volatile("cp.async.wait_group 0;" ::: "memory");
        __syncthreads();

        uint32_t aB = sb + (uint32_t)b * STG + sAoff;
        uint32_t bB = sb + (uint32_t)b * STG + sBoff;

        uint32_t hD[2][8][2];   // fp16x2 chunk accumulators
#pragma unroll
        for (int ks = 0; ks < 4; ks++) {
            uint32_t af[2][4], bf[4][4];
#pragma unroll
            for (int mt = 0; mt < 2; mt++) {
                uint32_t off = (uint32_t)(wm * 32 + mt * 16 + lr) * 128 + (uint32_t)lh * 16 + ks * 32;
                LDSM_X4(af[mt], aB + (off ^ ((off >> 3) & 0x70)));
            }
#pragma unroll
            for (int i = 0; i < 4; i++) {
                uint32_t off = (uint32_t)(wn * 64 + i * 16 + lr) * 128 + (uint32_t)lh * 16 + ks * 32;
                LDSM_X4(bf[i], bB + (off ^ ((off >> 3) & 0x70)));
            }
#pragma unroll
            for (int mt = 0; mt < 2; mt++)
#pragma unroll
                for (int i = 0; i < 4; i++) {
                    if (ks == 0) {
                        MMA_H16(hD[mt][2 * i][0],     hD[mt][2 * i][1],
                                af[mt][0], af[mt][1], af[mt][2], af[mt][3],
                                bf[i][0], bf[i][2], 0u, 0u);
                        MMA_H16(hD[mt][2 * i + 1][0], hD[mt][2 * i + 1][1],
                                af[mt][0], af[mt][1], af[mt][2], af[mt][3],
                                bf[i][1], bf[i][3], 0u, 0u);
                    } else {
                        MMA_H16(hD[mt][2 * i][0],     hD[mt][2 * i][1],
                                af[mt][0], af[mt][1], af[mt][2], af[mt][3],
                                bf[i][0], bf[i][2], hD[mt][2 * i][0], hD[mt][2 * i][1]);
                        MMA_H16(hD[mt][2 * i + 1][0], hD[mt][2 * i + 1][1],
                                af[mt][0], af[mt][1], af[mt][2], af[mt][3],
                                bf[i][1], bf[i][3], hD[mt][2 * i + 1][0], hD[mt][2 * i + 1][1]);
                    }
                }
        }
        // promote chunk sums to fp32
#pragma unroll
        for (int mt = 0; mt < 2; mt++)
#pragma unroll
            for (int nt = 0; nt < 8; nt++) {
                float2 lo = __half22float2(*reinterpret_cast<__half2*>(&hD[mt][nt][0]));
                float2 hi = __half22float2(*reinterpret_cast<__half2*>(&hD[mt][nt][1]));
                accf[mt][nt][0] += lo.x;
                accf[mt][nt][1] += lo.y;
                accf[mt][nt][2] += hi.x;
                accf[mt][nt][3] += hi.y;
            }
        __syncthreads();

        if (t + 2 < NCH) {
            g_load_chunk(sb, b, t + 2, m0, o0, tid);
            asm volatile("cp.async.commit_group;" ::: "memory");
        }
    }

    // epilogue exchange: M-warps stash relu(acc), O-warps add + store
    float* sm = (float*)smem;
    int gid = l >> 2, tig = l & 3;
    if (wmat == 1) {
#pragma unroll
        for (int mt = 0; mt < 2; mt++)
#pragma unroll
            for (int nt = 0; nt < 8; nt++) {
                int r0 = wm * 32 + mt * 16 + gid;
                int col = wn * 64 + nt * 8 + tig * 2;
                *(float2*)&sm[r0 * LDE + col] =
                    make_float2(fmaxf(accf[mt][nt][0], 0.f), fmaxf(accf[mt][nt][1], 0.f));
                *(float2*)&sm[(r0 + 8) * LDE + col] =
                    make_float2(fmaxf(accf[mt][nt][2], 0.f), fmaxf(accf[mt][nt][3], 0.f));
            }
    }
    __syncthreads();
    if (wmat == 0) {
#pragma unroll
        for (int mt = 0; mt < 2; mt++)
#pragma unroll
            for (int nt = 0; nt < 8; nt++) {
                int r0 = wm * 32 + mt * 16 + gid;
                int col = wn * 64 + nt * 8 + tig * 2;
                float2 e0 = *(float2*)&sm[r0 * LDE + col];
                float2 e1 = *(float2*)&sm[(r0 + 8) * LDE + col];
                float* p0 = out + (size_t)(m0 + r0) * OO + o0 + col;
                float* p1 = p0 + 8 * OO;
                *(float2*)p0 = make_float2(accf[mt][nt][0] + e0.x, accf[mt][nt][1] + e0.y);
                *(float2*)p1 = make_float2(accf[mt][nt][2] + e1.x, accf[mt][nt][3] + e1.y);
            }
    }
}

// ---------------- launch ----------------
extern "C" void kernel_launch(void* const* d_in, const int* in_sizes, int n_in,
                              void* d_out, int out_size) {
    const float* x     = (const float*)d_in[0];
    const float* adj   = (const float*)d_in[1];
    const int*   ei    = (const int*)d_in[2];
    const int*   ej    = (const int*)d_in[3];
    const float* gamma = (const float*)d_in[4];
    const float* beta  = (const float*)d_in[5];
    const float* wdir  = (const float*)d_in[6];
    const float* Wm    = (const float*)d_in[7];
    const float* Wo    = (const float*)d_in[8];
    float* out = (float*)d_out;

    cudaFuncSetAttribute(k_gemm, cudaFuncAttributeMaxDynamicSharedMemorySize, SMEM_G);

    k_packw<<<(OO * CC) / 1024, 256>>>(Wm, Wo);
    k_stats<<<NN / 8, CC>>>(x);
    k_adjW<<<NN, CC>>>(adj, ei, ej, gamma, beta, wdir);

    dim3 grid(MTOT / 64, OO / 128);   // 448 x 4
    k_gemm<<<grid, 256, SMEM_G>>>(out);
}

// round 16
// speedup vs baseline: 1.1713x; 1.1713x over previous
#include <cuda_runtime.h>
#include <cuda_fp16.h>
#include <cstdint>
#include <stdint.h>
#include <math.h>

#define NN 2048
#define KK 14
#define CC 512
#define OO 512
#define EE 78
#define BN_EPS 1e-5f
#define MTOT (NN * KK)     // 28672

// ---------------- device scratch ----------------
__device__ float g_S1[CC];
__device__ float g_Q[CC];
__device__ __half g_Ah[(size_t)MTOT * CC];     // fp16 X    (28 MB)
__device__ __half g_Ag[(size_t)MTOT * CC];     // fp16 agg  (28 MB)
__device__ __half g_Bh[2ull * OO * CC];        // fp16 Wo(0), Wm(1)

__device__ __forceinline__ uint32_t h2u(__half2 h) { return *reinterpret_cast<uint32_t*>(&h); }

#define LDSM_X4(r, addr)                                                      \
    asm volatile("ldmatrix.sync.aligned.m8n8.x4.shared.b16 {%0,%1,%2,%3}, [%4];" \
                 : "=r"((r)[0]), "=r"((r)[1]), "=r"((r)[2]), "=r"((r)[3])     \
                 : "r"(addr))
#define MMA_F16(Cr, A0, A1, A2, A3, B0, B1)                                   \
    asm volatile("mma.sync.aligned.m16n8k16.row.col.f32.f16.f16.f32 "          \
                 "{%0,%1,%2,%3}, {%4,%5,%6,%7}, {%8,%9}, {%0,%1,%2,%3};\n"     \
                 : "+f"(Cr[0]), "+f"(Cr[1]), "+f"(Cr[2]), "+f"(Cr[3])          \
                 : "r"(A0), "r"(A1), "r"(A2), "r"(A3), "r"(B0), "r"(B1))

// ---------------- pack weights to fp16 (+ zero stats in block 0) ----------------
__global__ __launch_bounds__(256) void k_packw(const float* __restrict__ Wm,
                                               const float* __restrict__ Wo) {
    if (blockIdx.x == 0) {
        int t = threadIdx.x;
        g_S1[t] = 0.f; g_S1[t + 256] = 0.f;
        g_Q[t]  = 0.f; g_Q[t + 256]  = 0.f;
    }
    int i = blockIdx.x * 1024 + threadIdx.x;
#pragma unroll
    for (int r = 0; r < 4; r++, i += 256) {
        g_Bh[i]           = __float2half(Wo[i]);
        g_Bh[OO * CC + i] = __float2half(Wm[i]);
    }
}

// ---------------- per-channel BN statistics + fp16 pack of X ----------------
// 512 blocks x 4 rows: >1 full wave for better HBM utilization.
__global__ __launch_bounds__(512) void k_stats(const float* __restrict__ x) {
    int c = threadIdx.x;
    int n0 = blockIdx.x * 4;
    float s1a = 0.f, qa = 0.f;
#pragma unroll
    for (int r = 0; r < 4; r++) {
        int n = n0 + r;
        const float* p = x + (size_t)n * (KK * CC) + c;
        __half* ah = g_Ah + ((size_t)n * KK) * CC + c;
        float g = p[13 * CC];
        ah[13 * CC] = __float2half(g);
        float s1 = 0.f, s2 = 0.f, ws = 0.f;
#pragma unroll
        for (int k = 0; k < 13; k++) {
            float v = p[k * CC];
            ah[k * CC] = __float2half(v);
            float d = fabsf(v - g);
            s1 += d;
            s2 += d * d;
            ws += (float)(12 - 2 * k) * d;
        }
        s1a += ws;
        qa  += 13.f * s2 - s1 * s1;
    }
    atomicAdd(&g_S1[c], s1a);
    atomicAdd(&g_Q[c],  qa);
}

// ---------------- adjacency + tensor-core aggregation (R13 proven) ----------------
__global__ __launch_bounds__(512, 3) void k_adjW(const float* __restrict__ adjin,
                                                 const int* __restrict__ ei,
                                                 const int* __restrict__ ej,
                                                 const float* __restrict__ gamma,
                                                 const float* __restrict__ beta,
                                                 const float* __restrict__ wdir) {
    int n = blockIdx.x;
    int c = threadIdx.x;
    int lane = c & 31, warp = c >> 5;

    __shared__ char buf[13 * 512 * 4];   // phase1: sd[13][512] f32 ; phase2: Xs[512][24] f16
    __shared__ float red[16];
    __shared__ float s_cst;
    __shared__ float sp[13];
    __shared__ float W[14][14];
    __shared__ float rn[14];
    __shared__ __half Whi[16][24];
    __shared__ __half Wlo[16][24];

    float (*sd)[CC] = (float (*)[CC])buf;

    const float inv = 1.f / (float)((size_t)NN * EE);
    float mean = 15.f * g_S1[c] * inv;
    float ms   = 225.f * g_Q[c] * inv;
    float var  = ms - mean * mean;
    float w    = wdir[c];
    float u    = gamma[c] * rsqrtf(var + BN_EPS) * w;
    float part = beta[c] * w - mean * u;
#pragma unroll
    for (int off = 16; off > 0; off >>= 1)
        part += __shfl_xor_sync(0xffffffffu, part, off);
    if (lane == 0) red[warp] = part;

    const __half* ah = g_Ah + ((size_t)n * KK) * CC + c;
    __half hv[14];
#pragma unroll
    for (int k = 0; k < 14; k++) hv[k] = ah[k * CC];
    {
        float g = __half2float(hv[13]);
#pragma unroll
        for (int k = 0; k < 13; k++)
            sd[k][c] = fabsf(__half2float(hv[k]) - g) * u;
    }
    if (c < 196) W[c / 14][c % 14] = adjin[c];
    __syncthreads();

    if (c == 0) {
        float s = 0.f;
#pragma unroll
        for (int i = 0; i < 16; i++) s += red[i];
        s_cst = s;
    }
    if (warp < 13) {
        float s = 0.f;
#pragma unroll
        for (int i = 0; i < 16; i++) s += sd[warp][lane + 32 * i];
        s += __shfl_xor_sync(0xffffffffu, s, 16);
        s += __shfl_xor_sync(0xffffffffu, s, 8);
        s += __shfl_xor_sync(0xffffffffu, s, 4);
        s += __shfl_xor_sync(0xffffffffu, s, 2);
        s += __shfl_xor_sync(0xffffffffu, s, 1);
        if (lane == 0) sp[warp] = s;
    }
    __syncthreads();   // sd dead after this point

    if (c < EE) {
        int i = ei[c], j = ej[c];
        float z = 15.f * (sp[i] - sp[j]) + s_cst;
        float a = 1.f / (1.f + expf(-4.f * z));
        W[i][j] = 2.f * a * adjin[i * 14 + j];
        W[j][i] = 2.f * (1.f - a) * adjin[j * 14 + i];
    }
    {
        char* row = buf + (size_t)c * 48;
        uint4 u0, u1;
        u0.x = h2u(__halves2half2(hv[0],  hv[1]));
        u0.y = h2u(__halves2half2(hv[2],  hv[3]));
        u0.z = h2u(__halves2half2(hv[4],  hv[5]));
        u0.w = h2u(__halves2half2(hv[6],  hv[7]));
        u1.x = h2u(__halves2half2(hv[8],  hv[9]));
        u1.y = h2u(__halves2half2(hv[10], hv[11]));
        u1.z = h2u(__halves2half2(hv[12], hv[13]));
        u1.w = 0u;                                    // k = 14,15 zero pad
        *(uint4*)row        = u0;
        *(uint4*)(row + 16) = u1;
    }
    __syncthreads();

    if (c < 14) {
        float s = 0.f;
#pragma unroll
        for (int j = 0; j < 14; j++) s += fabsf(W[c][j]);
        rn[c] = 1.f / fmaxf(s, 1e-12f);
    }
    __syncthreads();

    if (c < 256) {   // build fp16 digit pair of W*rn, zero-padded to 16x16
        int i = c >> 4, j = c & 15;
        float v = (i < 14 && j < 14) ? W[i][j] * rn[i] : 0.f;
        __half hi = __float2half(v);
        Whi[i][j] = hi;
        Wlo[i][j] = __float2half(v - __half2float(hi));
    }
    __syncthreads();

    // Phase 2: each warp computes agg cols [32w, 32w+32)
    {
        int lr = lane & 15, lh = lane >> 4;
        uint32_t xsb  = (uint32_t)__cvta_generic_to_shared(buf);
        uint32_t whib = (uint32_t)__cvta_generic_to_shared(&Whi[0][0]);
        uint32_t wlob = (uint32_t)__cvta_generic_to_shared(&Wlo[0][0]);
        uint32_t aw = (uint32_t)(lr * 48 + lh * 16);
        uint32_t bx0 = xsb + (uint32_t)((warp * 32 + lr) * 48 + lh * 16);
        uint32_t bx1 = bx0 + 16 * 48;

        uint32_t ahi[4], alo[4], bf0[4], bf1[4];
        LDSM_X4(ahi, whib + aw);
        LDSM_X4(alo, wlob + aw);
        LDSM_X4(bf0, bx0);
        LDSM_X4(bf1, bx1);

        float acc[4][4];
#pragma unroll
        for (int t = 0; t < 4; t++)
#pragma unroll
            for (int i = 0; i < 4; i++) acc[t][i] = 0.f;

        MMA_F16(acc[0], ahi[0], ahi[1], ahi[2], ahi[3], bf0[0], bf0[2]);
        MMA_F16(acc[0], alo[0], alo[1], alo[2], alo[3], bf0[0], bf0[2]);
        MMA_F16(acc[1], ahi[0], ahi[1], ahi[2], ahi[3], bf0[1], bf0[3]);
        MMA_F16(acc[1], alo[0], alo[1], alo[2], alo[3], bf0[1], bf0[3]);
        MMA_F16(acc[2], ahi[0], ahi[1], ahi[2], ahi[3], bf1[0], bf1[2]);
        MMA_F16(acc[2], alo[0], alo[1], alo[2], alo[3], bf1[0], bf1[2]);
        MMA_F16(acc[3], ahi[0], ahi[1], ahi[2], ahi[3], bf1[1], bf1[3]);
        MMA_F16(acc[3], alo[0], alo[1], alo[2], alo[3], bf1[1], bf1[3]);

        int gid = lane >> 2, tig = lane & 3;
        __half* ag = g_Ag + ((size_t)n * KK) * CC;
#pragma unroll
        for (int t = 0; t < 4; t++) {
            int col = warp * 32 + t * 8 + tig * 2;
            *(__half2*)&ag[(size_t)gid * CC + col] = __floats2half2_rn(acc[t][0], acc[t][1]);
            if (gid + 8 < 14)
                *(__half2*)&ag[(size_t)(gid + 8) * CC + col] = __floats2half2_rn(acc[t][2], acc[t][3]);
        }
    }
}

// ---------------- fused dual fp16 GEMM (R9/R13 version, frozen at 91us) ----------------
#define S_AX 0
#define S_AG 8192
#define S_BO 16384
#define S_BM 32768
#define STG  49152
#define SMEM_G (2 * STG)   // 98304

__device__ __forceinline__ void cpa16(uint32_t dst, const void* src) {
    asm volatile("cp.async.cg.shared.global [%0], [%1], 16;" :: "r"(dst), "l"(src));
}

__device__ __forceinline__ void g_load_chunk(uint32_t sb, int stg, int t,
                                             int m0, int o0, int tid) {
    uint32_t base = sb + (uint32_t)stg * STG;
    const __half* Ax = g_Ah + (size_t)m0 * CC + t * 64;
    const __half* Ag = g_Ag + (size_t)m0 * CC + t * 64;
    const __half* Bo = g_Bh + t * 64;
    const __half* Bm = g_Bh + (size_t)OO * CC + t * 64;
#pragma unroll
    for (int i = 0; i < 2; i++) {
        int idx = tid + i * 256;
        int r = idx >> 3, c = idx & 7;
        uint32_t off = (uint32_t)r * 128 + (uint32_t)c * 16;
        uint32_t sw = off ^ ((off >> 3) & 0x70);
        cpa16(base + S_AX + sw, Ax + (size_t)r * CC + c * 8);
        cpa16(base + S_AG + sw, Ag + (size_t)r * CC + c * 8);
    }
#pragma unroll
    for (int i = 0; i < 4; i++) {
        int idx = tid + i * 256;
        int r = idx >> 3, c = idx & 7;
        uint32_t off = (uint32_t)r * 128 + (uint32_t)c * 16;
        uint32_t sw = off ^ ((off >> 3) & 0x70);
        cpa16(base + S_BO + sw, Bo + (size_t)(o0 + r) * CC + c * 8);
        cpa16(base + S_BM + sw, Bm + (size_t)(o0 + r) * CC + c * 8);
    }
}

__global__ __launch_bounds__(256, 2) void k_gemm(float* __restrict__ out) {
    extern __shared__ char smem[];
    uint32_t sb = (uint32_t)__cvta_generic_to_shared(smem);
    int tid = threadIdx.x;
    int w = tid >> 5, l = tid & 31;
    int wm = w & 1;
    int wn = w >> 1;
    int m0 = blockIdx.x * 64;
    int o0 = blockIdx.y * 128;
    int lr = l & 15, lh = l >> 4;

    float accO[2][4][4], accM[2][4][4];
#pragma unroll
    for (int mt = 0; mt < 2; mt++)
#pragma unroll
        for (int nt = 0; nt < 4; nt++)
#pragma unroll
            for (int i = 0; i < 4; i++) { accO[mt][nt][i] = 0.f; accM[mt][nt][i] = 0.f; }

    g_load_chunk(sb, 0, 0, m0, o0, tid);
    asm volatile("cp.async.commit_group;" ::: "memory");
    g_load_chunk(sb, 1, 1, m0, o0, tid);
    asm volatile("cp.async.commit_group;" ::: "memory");

    const int NCH = CC / 64;   // 8
    for (int t = 0; t < NCH; t++) {
        int b = t & 1;
        if (t < NCH - 1) asm volatile("cp.async.wait_group 1;" ::: "memory");
        else             asm volatile("cp.async.wait_group 0;" ::: "memory");
        __syncthreads();

        uint32_t base = sb + (uint32_t)b * STG;
#pragma unroll
        for (int ks = 0; ks < 4; ks++) {
            uint32_t arow = (uint32_t)(wm * 32 + lr) * 128 + (uint32_t)lh * 16 + ks * 32;
            uint32_t brow = (uint32_t)(wn * 32 + lr) * 128 + (uint32_t)lh * 16 + ks * 32;
            uint32_t a0 = arow ^ ((arow >> 3) & 0x70);
            uint32_t a1 = (arow + 16 * 128) ^ (((arow + 16 * 128) >> 3) & 0x70);
            uint32_t b0 = brow ^ ((brow >> 3) & 0x70);
            uint32_t b1 = (brow + 16 * 128) ^ (((brow + 16 * 128) >> 3) & 0x70);
            {
                uint32_t af[2][4], bf[2][4];
                LDSM_X4(af[0], base + S_AX + a0);
                LDSM_X4(af[1], base + S_AX + a1);
                LDSM_X4(bf[0], base + S_BO + b0);
                LDSM_X4(bf[1], base + S_BO + b1);
#pragma unroll
                for (int mt = 0; mt < 2; mt++)
#pragma unroll
                    for (int i = 0; i < 2; i++) {
                        MMA_F16(accO[mt][2 * i],     af[mt][0], af[mt][1], af[mt][2], af[mt][3], bf[i][0], bf[i][2]);
                        MMA_F16(accO[mt][2 * i + 1], af[mt][0], af[mt][1], af[mt][2], af[mt][3], bf[i][1], bf[i][3]);
                    }
            }
            {
                uint32_t af[2][4], bf[2][4];
                LDSM_X4(af[0], base + S_AG + a0);
                LDSM_X4(af[1], base + S_AG + a1);
                LDSM_X4(bf[0], base + S_BM + b0);
                LDSM_X4(bf[1], base + S_BM + b1);
#pragma unroll
                for (int mt = 0; mt < 2; mt++)
#pragma unroll
                    for (int i = 0; i < 2; i++) {
                        MMA_F16(accM[mt][2 * i],     af[mt][0], af[mt][1], af[mt][2], af[mt][3], bf[i][0], bf[i][2]);
                        MMA_F16(accM[mt][2 * i + 1], af[mt][0], af[mt][1], af[mt][2], af[mt][3], bf[i][1], bf[i][3]);
                    }
            }
        }
        __syncthreads();

        if (t + 2 < NCH) {
            g_load_chunk(sb, b, t + 2, m0, o0, tid);
            asm volatile("cp.async.commit_group;" ::: "memory");
        }
    }

    int gid = l >> 2, tig = l & 3;
#pragma unroll
    for (int mt = 0; mt < 2; mt++) {
#pragma unroll
        for (int nt = 0; nt < 4; nt++) {
            float* p0 = out + (size_t)(m0 + wm * 32 + mt * 16 + gid) * OO + o0 + wn * 32 + nt * 8 + tig * 2;
            float* p1 = p0 + 8 * OO;
            *(float2*)p0 = make_float2(fmaxf(accM[mt][nt][0], 0.f) + accO[mt][nt][0],
                                       fmaxf(accM[mt][nt][1], 0.f) + accO[mt][nt][1]);
            *(float2*)p1 = make_float2(fmaxf(accM[mt][nt][2], 0.f) + accO[mt][nt][2],
                                       fmaxf(accM[mt][nt][3], 0.f) + accO[mt][nt][3]);
        }
    }
}

// ---------------- launch ----------------
extern "C" void kernel_launch(void* const* d_in, const int* in_sizes, int n_in,
                              void* d_out, int out_size) {
    const float* x     = (const float*)d_in[0];
    const float* adj   = (const float*)d_in[1];
    const int*   ei    = (const int*)d_in[2];
    const int*   ej    = (const int*)d_in[3];
    const float* gamma = (const float*)d_in[4];
    const float* beta  = (const float*)d_in[5];
    const float* wdir  = (const float*)d_in[6];
    const float* Wm    = (const float*)d_in[7];
    const float* Wo    = (const float*)d_in[8];
    float* out = (float*)d_out;

    cudaFuncSetAttribute(k_gemm, cudaFuncAttributeMaxDynamicSharedMemorySize, SMEM_G);

    k_packw<<<(OO * CC) / 1024, 256>>>(Wm, Wo);
    k_stats<<<NN / 4, CC>>>(x);
    k_adjW<<<NN, CC>>>(adj, ei, ej, gamma, beta, wdir);

    dim3 grid(MTOT / 64, OO / 128);   // 448 x 4
    k_gemm<<<grid, 256, SMEM_G>>>(out);
}